// round 1
// baseline (speedup 1.0000x reference)
#include <cuda_runtime.h>
#include <cuda_bf16.h>
#include <cstdint>

// Problem constants (fixed shapes for this bench)
#define NSPLAT 6144
#define NCAM   6
#define NCH    32
#define IMH    80
#define IMW    80
#define SORTN  8192   // next pow2 >= NSPLAT

#define LOWPASS 0.3f
#define NEARCLIP 0.2f

// ---------------- device scratch (no allocations allowed) ----------------
__device__ float g_u [NCAM * NSPLAT];
__device__ float g_v [NCAM * NSPLAT];
__device__ float g_ia[NCAM * NSPLAT];
__device__ float g_ib[NCAM * NSPLAT];
__device__ float g_ic[NCAM * NSPLAT];
__device__ float g_op[NCAM * NSPLAT];
__device__ unsigned long long g_keys[NCAM * NSPLAT];
__device__ int g_order[NCAM * NSPLAT];

// ---------------- preprocess: per camera, per splat ----------------
__global__ void preproc_kernel(const float* __restrict__ density,
                               const float* __restrict__ cam_rot,
                               const float* __restrict__ cam_trans,
                               const float* __restrict__ cam_intr,
                               const float* __restrict__ pc_xyz,
                               const float* __restrict__ scales,
                               const float* __restrict__ rots)
{
    int i   = blockIdx.x * blockDim.x + threadIdx.x;
    int cam = blockIdx.y;
    if (i >= NSPLAT) return;

    float x = pc_xyz[3*i+0], y = pc_xyz[3*i+1], z = pc_xyz[3*i+2];
    const float* Rc = cam_rot + cam*9;
    float R0 = Rc[0], R1 = Rc[1], R2 = Rc[2];
    float R3 = Rc[3], R4 = Rc[4], R5 = Rc[5];
    float R6 = Rc[6], R7 = Rc[7], R8 = Rc[8];
    float t0 = cam_trans[cam*3+0], t1 = cam_trans[cam*3+1], t2 = cam_trans[cam*3+2];
    float fx = cam_intr[cam*4+0], fy = cam_intr[cam*4+1];
    float cx = cam_intr[cam*4+2], cy = cam_intr[cam*4+3];

    float camx = R0*x + R1*y + R2*z + t0;
    float camy = R3*x + R4*y + R5*z + t1;
    // depth: no fma contraction, left-to-right, to reproduce exact tie groups
    float camz = __fadd_rn(__fadd_rn(__fadd_rn(__fmul_rn(R6,x), __fmul_rn(R7,y)),
                                     __fmul_rn(R8,z)), t2);

    bool valid = camz > NEARCLIP;
    float tz = fmaxf(camz, 1e-6f);

    float u = fx*camx/tz + cx;
    float v = fy*camy/tz + cy;

    float j00 =  fx/tz;
    float j02 = -fx*camx/(tz*tz);
    float j11 =  fy/tz;
    float j12 = -fy*camy/(tz*tz);

    // quaternion -> rotation
    float qw = rots[4*i+0], qx = rots[4*i+1], qy = rots[4*i+2], qz = rots[4*i+3];
    float Q00 = 1.f - 2.f*(qy*qy + qz*qz), Q01 = 2.f*(qx*qy - qw*qz), Q02 = 2.f*(qx*qz + qw*qy);
    float Q10 = 2.f*(qx*qy + qw*qz), Q11 = 1.f - 2.f*(qx*qx + qz*qz), Q12 = 2.f*(qy*qz - qw*qx);
    float Q20 = 2.f*(qx*qz - qw*qy), Q21 = 2.f*(qy*qz + qw*qx), Q22 = 1.f - 2.f*(qx*qx + qy*qy);
    float s = expf(scales[i]);

    // A = J @ Rcw  (2x3)
    float A00 = j00*R0 + j02*R6, A01 = j00*R1 + j02*R7, A02 = j00*R2 + j02*R8;
    float A10 = j11*R3 + j12*R6, A11 = j11*R4 + j12*R7, A12 = j11*R5 + j12*R8;

    // Bm = A @ (s*Q)  (2x3)
    float B00 = s*(A00*Q00 + A01*Q10 + A02*Q20);
    float B01 = s*(A00*Q01 + A01*Q11 + A02*Q21);
    float B02 = s*(A00*Q02 + A01*Q12 + A02*Q22);
    float B10 = s*(A10*Q00 + A11*Q10 + A12*Q20);
    float B11 = s*(A10*Q01 + A11*Q11 + A12*Q21);
    float B12 = s*(A10*Q02 + A11*Q12 + A12*Q22);

    float cov00 = B00*B00 + B01*B01 + B02*B02;
    float cov01 = B00*B10 + B01*B11 + B02*B12;
    float cov11 = B10*B10 + B11*B11 + B12*B12;

    float a  = cov00 + LOWPASS;
    float bb = cov01;
    float c  = cov11 + LOWPASS;
    float det = a*c - bb*bb;
    float ia =  c/det;
    float ib = -bb/det;
    float ic =  a/det;

    // softplus(density) folded with valid flag
    float d = density[i];
    float op = (d > 0.f) ? (d + log1pf(expf(-d))) : log1pf(expf(d));
    if (!valid) op = 0.f;

    float depth = valid ? tz : (tz + 1e6f);

    int o = cam*NSPLAT + i;
    g_u [o] = u;  g_v [o] = v;
    g_ia[o] = ia; g_ib[o] = ib; g_ic[o] = ic;
    g_op[o] = op;
    g_keys[o] = ((unsigned long long)__float_as_uint(depth) << 32) | (unsigned int)i;
}

// ---------------- stable sort: one block per camera, bitonic over 8192 u64 ----------------
__global__ void sort_kernel()
{
    extern __shared__ unsigned long long sk[];
    int cam = blockIdx.x;
    int tid = threadIdx.x;

    for (int i = tid; i < SORTN; i += blockDim.x)
        sk[i] = (i < NSPLAT) ? g_keys[cam*NSPLAT + i] : ~0ull;
    __syncthreads();

    for (int k = 2; k <= SORTN; k <<= 1) {
        for (int j = k >> 1; j > 0; j >>= 1) {
            for (int i = tid; i < SORTN; i += blockDim.x) {
                int ixj = i ^ j;
                if (ixj > i) {
                    unsigned long long a = sk[i], b = sk[ixj];
                    bool up = ((i & k) == 0);
                    if (up ? (a > b) : (a < b)) { sk[i] = b; sk[ixj] = a; }
                }
            }
            __syncthreads();
        }
    }

    for (int i = tid; i < NSPLAT; i += blockDim.x)
        g_order[cam*NSPLAT + i] = (int)(sk[i] & 0xffffffffull);
}

// ---------------- render: 16x8 pixel tile per 128-thread block ----------------
#define CHUNK 128

__global__ void __launch_bounds__(128)
render_kernel(const float* __restrict__ feats, float* __restrict__ out)
{
    int cam = blockIdx.z;
    int tid = threadIdx.x;
    int tx = tid & 15, ty = tid >> 4;
    int px = blockIdx.x * 16 + tx;
    int py = blockIdx.y * 8 + ty;
    float fpx = (float)px, fpy = (float)py;

    __shared__ float su[CHUNK], sv[CHUNK], sia[CHUNK], sib[CHUNK], sic[CHUNK], sop[CHUNK];
    __shared__ float4 sfeat[CHUNK * 8];   // XOR-swizzled [splat][8 float4]

    float T = 1.f;
    float acc[NCH];
    #pragma unroll
    for (int c = 0; c < NCH; c++) acc[c] = 0.f;

    const int* ord = g_order + cam*NSPLAT;
    const int cbase = cam*NSPLAT;

    for (int base = 0; base < NSPLAT; base += CHUNK) {
        // stage chunk
        {
            int sidx = base + tid;
            int idx = ord[sidx];            // NSPLAT % CHUNK == 0, always in range
            su [tid] = g_u [cbase + idx];
            sv [tid] = g_v [cbase + idx];
            sia[tid] = g_ia[cbase + idx];
            sib[tid] = g_ib[cbase + idx];
            sic[tid] = g_ic[cbase + idx];
            sop[tid] = g_op[cbase + idx];
            const float4* fr = (const float4*)feats + idx * 8;
            int sw = tid & 7;
            #pragma unroll
            for (int k = 0; k < 8; k++)
                sfeat[tid*8 + (k ^ sw)] = fr[k];
        }
        __syncthreads();

        for (int j = 0; j < CHUNK; j++) {
            float op = sop[j];              // warp-uniform branch
            if (op > 0.f) {
                float dx = fpx - su[j];
                float dy = fpy - sv[j];
                float power = -0.5f*(sia[j]*dx*dx + sic[j]*dy*dy) - sib[j]*dx*dy;
                float g = __expf(fminf(power, 0.f));
                float alpha = fminf(op * g, 0.99f);
                float w = T * alpha;
                if (w > 1e-10f) {
                    int jw = j & 7;
                    #pragma unroll
                    for (int k = 0; k < 8; k++) {
                        float4 f = sfeat[j*8 + (k ^ jw)];
                        acc[4*k+0] += w * f.x;
                        acc[4*k+1] += w * f.y;
                        acc[4*k+2] += w * f.z;
                        acc[4*k+3] += w * f.w;
                    }
                }
                T *= (1.f - alpha);
            }
        }

        if (!__syncthreads_or(T > 1e-6f)) break;
    }

    // out layout: (B=1, NC, C, H, W)
    #pragma unroll
    for (int c = 0; c < NCH; c++)
        out[((cam*NCH + c)*IMH + py)*IMW + px] = acc[c];
}

// ---------------- launch ----------------
extern "C" void kernel_launch(void* const* d_in, const int* in_sizes, int n_in,
                              void* d_out, int out_size)
{
    const float* vox_features = (const float*)d_in[0];
    const float* density      = (const float*)d_in[1];
    const float* cam_rot      = (const float*)d_in[2];
    const float* cam_trans    = (const float*)d_in[3];
    const float* cam_intr     = (const float*)d_in[4];
    const float* pc_xyz       = (const float*)d_in[5];
    const float* scales       = (const float*)d_in[6];
    const float* rots         = (const float*)d_in[7];
    float* out = (float*)d_out;

    static bool attr_set = false;
    if (!attr_set) {
        cudaFuncSetAttribute(sort_kernel,
                             cudaFuncAttributeMaxDynamicSharedMemorySize,
                             SORTN * sizeof(unsigned long long));
        attr_set = true;
    }

    dim3 pre_grid((NSPLAT + 127) / 128, NCAM);
    preproc_kernel<<<pre_grid, 128>>>(density, cam_rot, cam_trans, cam_intr,
                                      pc_xyz, scales, rots);

    sort_kernel<<<NCAM, 1024, SORTN * sizeof(unsigned long long)>>>();

    dim3 rg(IMW / 16, IMH / 8, NCAM);
    render_kernel<<<rg, 128>>>(vox_features, out);
}

// round 2
// speedup vs baseline: 3.5485x; 3.5485x over previous
#include <cuda_runtime.h>
#include <cuda_bf16.h>
#include <cstdint>

// Problem constants (fixed shapes for this bench)
#define NSPLAT 6144
#define NCOL   1024     // 32*32 depth columns (depth is z-independent)
#define ZPC    6        // splats per column
#define NCAM   6
#define NCH    32
#define IMH    80
#define IMW    80

#define LOWPASS 0.3f
#define NEARCLIP 0.2f

// ---------------- device scratch ----------------
__device__ float4 g_p0[NCAM * NSPLAT];   // u, v, 0.5*ia, ib
__device__ float4 g_p1[NCAM * NSPLAT];   // 0.5*ic, op, ex, ey
__device__ unsigned long long g_colkey[NCAM * NCOL];
__device__ int g_order[NCAM * NSPLAT];

// ---------------- preprocess ----------------
__global__ void preproc_kernel(const float* __restrict__ density,
                               const float* __restrict__ cam_rot,
                               const float* __restrict__ cam_trans,
                               const float* __restrict__ cam_intr,
                               const float* __restrict__ pc_xyz,
                               const float* __restrict__ scales,
                               const float* __restrict__ rots)
{
    int i   = blockIdx.x * blockDim.x + threadIdx.x;
    int cam = blockIdx.y;
    if (i >= NSPLAT) return;

    float x = pc_xyz[3*i+0], y = pc_xyz[3*i+1], z = pc_xyz[3*i+2];
    const float* Rc = cam_rot + cam*9;
    float R0 = Rc[0], R1 = Rc[1], R2 = Rc[2];
    float R3 = Rc[3], R4 = Rc[4], R5 = Rc[5];
    float R6 = Rc[6], R7 = Rc[7], R8 = Rc[8];
    float t0 = cam_trans[cam*3+0], t1 = cam_trans[cam*3+1], t2 = cam_trans[cam*3+2];
    float fx = cam_intr[cam*4+0], fy = cam_intr[cam*4+1];
    float cx = cam_intr[cam*4+2], cy = cam_intr[cam*4+3];

    float camx = R0*x + R1*y + R2*z + t0;
    float camy = R3*x + R4*y + R5*z + t1;
    // depth: no fma contraction, left-to-right, to reproduce exact tie groups
    float camz = __fadd_rn(__fadd_rn(__fadd_rn(__fmul_rn(R6,x), __fmul_rn(R7,y)),
                                     __fmul_rn(R8,z)), t2);

    bool valid = camz > NEARCLIP;
    float tz = fmaxf(camz, 1e-6f);

    float u = fx*camx/tz + cx;
    float v = fy*camy/tz + cy;

    float j00 =  fx/tz;
    float j02 = -fx*camx/(tz*tz);
    float j11 =  fy/tz;
    float j12 = -fy*camy/(tz*tz);

    // quaternion -> rotation
    float qw = rots[4*i+0], qx = rots[4*i+1], qy = rots[4*i+2], qz = rots[4*i+3];
    float Q00 = 1.f - 2.f*(qy*qy + qz*qz), Q01 = 2.f*(qx*qy - qw*qz), Q02 = 2.f*(qx*qz + qw*qy);
    float Q10 = 2.f*(qx*qy + qw*qz), Q11 = 1.f - 2.f*(qx*qx + qz*qz), Q12 = 2.f*(qy*qz - qw*qx);
    float Q20 = 2.f*(qx*qz - qw*qy), Q21 = 2.f*(qy*qz + qw*qx), Q22 = 1.f - 2.f*(qx*qx + qy*qy);
    float s = expf(scales[i]);

    // A = J @ Rcw  (2x3)
    float A00 = j00*R0 + j02*R6, A01 = j00*R1 + j02*R7, A02 = j00*R2 + j02*R8;
    float A10 = j11*R3 + j12*R6, A11 = j11*R4 + j12*R7, A12 = j11*R5 + j12*R8;

    // Bm = A @ (s*Q)  (2x3)
    float B00 = s*(A00*Q00 + A01*Q10 + A02*Q20);
    float B01 = s*(A00*Q01 + A01*Q11 + A02*Q21);
    float B02 = s*(A00*Q02 + A01*Q12 + A02*Q22);
    float B10 = s*(A10*Q00 + A11*Q10 + A12*Q20);
    float B11 = s*(A10*Q01 + A11*Q11 + A12*Q21);
    float B12 = s*(A10*Q02 + A11*Q12 + A12*Q22);

    float cov00 = B00*B00 + B01*B01 + B02*B02;
    float cov01 = B00*B10 + B01*B11 + B02*B12;
    float cov11 = B10*B10 + B11*B11 + B12*B12;

    float a  = cov00 + LOWPASS;
    float bb = cov01;
    float c  = cov11 + LOWPASS;
    float det = a*c - bb*bb;
    float ia =  c/det;
    float ib = -bb/det;
    float ic =  a/det;

    // softplus(density) folded with valid flag
    float d = density[i];
    float op = (d > 0.f) ? (d + log1pf(expf(-d))) : log1pf(expf(d));
    if (!valid) op = 0.f;

    int o = cam*NSPLAT + i;
    g_p0[o] = make_float4(u, v, 0.5f*ia, ib);
    g_p1[o] = make_float4(0.5f*ic, op, sqrtf(a), sqrtf(c));

    // depth column key (depth independent of z; one writer per column)
    if ((i % ZPC) == 0) {
        float depth = valid ? tz : (tz + 1e6f);
        int col = i / ZPC;
        g_colkey[cam*NCOL + col] =
            ((unsigned long long)__float_as_uint(depth) << 32) | (unsigned int)col;
    }
}

// ---------------- sort 1024 column keys per camera, expand to splat order ----------------
__global__ void sort_kernel()
{
    __shared__ unsigned long long sk[NCOL];
    int cam = blockIdx.x;
    int tid = threadIdx.x;   // 512 threads

    sk[tid]       = g_colkey[cam*NCOL + tid];
    sk[tid + 512] = g_colkey[cam*NCOL + tid + 512];
    __syncthreads();

    for (int k = 2; k <= NCOL; k <<= 1) {
        for (int j = k >> 1; j > 0; j >>= 1) {
            for (int i = tid; i < NCOL; i += 512) {
                int ixj = i ^ j;
                if (ixj > i) {
                    unsigned long long av = sk[i], bv = sk[ixj];
                    bool up = ((i & k) == 0);
                    if (up ? (av > bv) : (av < bv)) { sk[i] = bv; sk[ixj] = av; }
                }
            }
            __syncthreads();
        }
    }

    for (int r = tid; r < NCOL; r += 512) {
        int col = (int)(sk[r] & 0xffffffffull);
        int obase = cam*NSPLAT + r*ZPC;
        int ibase = col*ZPC;
        #pragma unroll
        for (int kzz = 0; kzz < ZPC; kzz++)
            g_order[obase + kzz] = ibase + kzz;
    }
}

// ---------------- render: 16x8 pixel tile per 128-thread block ----------------
#define CHUNK 128

__global__ void __launch_bounds__(128)
render_kernel(const float* __restrict__ feats, float* __restrict__ out)
{
    int cam = blockIdx.z;
    int tid = threadIdx.x;
    int tx = tid & 15, ty = tid >> 4;
    int px = blockIdx.x * 16 + tx;
    int py = blockIdx.y * 8 + ty;
    float fpx = (float)px, fpy = (float)py;

    float x0 = (float)(blockIdx.x * 16), x1 = x0 + 15.f;
    float y0 = (float)(blockIdx.y * 8),  y1 = y0 + 7.f;

    __shared__ float4 spa[CHUNK], spb[CHUNK];
    __shared__ float4 sfeat[CHUNK * 8];   // XOR-swizzled [slot][8 float4]
    __shared__ int warpcnt[4];

    float T = 1.f;
    float acc[NCH];
    #pragma unroll
    for (int c = 0; c < NCH; c++) acc[c] = 0.f;

    const int* ord = g_order + cam*NSPLAT;
    const float4* gp0 = g_p0 + cam*NSPLAT;
    const float4* gp1 = g_p1 + cam*NSPLAT;
    int lane = tid & 31, warp = tid >> 5;

    for (int base = 0; base < NSPLAT; base += CHUNK) {
        int idx = ord[base + tid];
        float4 pa = gp0[idx];   // u, v, hia, ib
        float4 pb = gp1[idx];   // hic, op, ex, ey

        // conservative tile cull: alpha_max over tile >= ~1e-8
        bool keep = false;
        float op = pb.y;
        if (op > 1e-8f) {
            float t = __logf(op) + 19.0f;      // ln(op) + ln(1e8) + margin
            float s = sqrtf(2.f * t);
            float dxn = fmaxf(fmaxf(x0 - pa.x, pa.x - x1), 0.f);
            float dyn = fmaxf(fmaxf(y0 - pa.y, pa.y - y1), 0.f);
            keep = (dxn <= pb.z * s) && (dyn <= pb.w * s);
        }

        unsigned ball = __ballot_sync(0xffffffffu, keep);
        if (lane == 0) warpcnt[warp] = __popc(ball);
        __syncthreads();

        int off = 0;
        #pragma unroll
        for (int wct = 0; wct < 4; wct++) {
            int cwc = warpcnt[wct];
            if (wct < warp) off += cwc;
        }
        int total = warpcnt[0] + warpcnt[1] + warpcnt[2] + warpcnt[3];

        if (keep) {
            int pos = off + __popc(ball & ((1u << lane) - 1u));
            spa[pos] = pa;
            spb[pos] = pb;
            const float4* fr = (const float4*)feats + idx * 8;
            int sw = pos & 7;
            #pragma unroll
            for (int k = 0; k < 8; k++)
                sfeat[pos*8 + (k ^ sw)] = fr[k];
        }
        __syncthreads();

        for (int j = 0; j < total; j++) {
            float4 a = spa[j];
            float4 b = spb[j];
            float dx = fpx - a.x;
            float dy = fpy - a.y;
            float power = -(a.z*dx*dx + b.x*dy*dy + a.w*dx*dy);
            float g = __expf(fminf(power, 0.f));
            float alpha = fminf(b.y * g, 0.99f);
            float w = T * alpha;
            if (w > 1e-10f) {
                int jw = j & 7;
                #pragma unroll
                for (int k = 0; k < 8; k++) {
                    float4 f = sfeat[j*8 + (k ^ jw)];
                    acc[4*k+0] += w * f.x;
                    acc[4*k+1] += w * f.y;
                    acc[4*k+2] += w * f.z;
                    acc[4*k+3] += w * f.w;
                }
            }
            T *= (1.f - alpha);
        }

        if (!__syncthreads_or(T > 1e-6f)) break;
    }

    // out layout: (B=1, NC, C, H, W)
    #pragma unroll
    for (int c = 0; c < NCH; c++)
        out[((cam*NCH + c)*IMH + py)*IMW + px] = acc[c];
}

// ---------------- launch ----------------
extern "C" void kernel_launch(void* const* d_in, const int* in_sizes, int n_in,
                              void* d_out, int out_size)
{
    const float* vox_features = (const float*)d_in[0];
    const float* density      = (const float*)d_in[1];
    const float* cam_rot      = (const float*)d_in[2];
    const float* cam_trans    = (const float*)d_in[3];
    const float* cam_intr     = (const float*)d_in[4];
    const float* pc_xyz       = (const float*)d_in[5];
    const float* scales       = (const float*)d_in[6];
    const float* rots         = (const float*)d_in[7];
    float* out = (float*)d_out;

    dim3 pre_grid((NSPLAT + 127) / 128, NCAM);
    preproc_kernel<<<pre_grid, 128>>>(density, cam_rot, cam_trans, cam_intr,
                                      pc_xyz, scales, rots);

    sort_kernel<<<NCAM, 512>>>();

    dim3 rg(IMW / 16, IMH / 8, NCAM);
    render_kernel<<<rg, 128>>>(vox_features, out);
}